// round 15
// baseline (speedup 1.0000x reference)
#include <cuda_runtime.h>
#include <cuda_bf16.h>

// Problem constants (fixed shapes from reference setup_inputs)
#define NN 40000
#define FD 64
#define KNB 24
#define EE (NN * KNB)        // 960000 candidate edges (= E_ADJ too)
#define OMEGA_C 0.9f

// ---------------- scratch (device globals; no allocation allowed) ----------
__device__ float g_xw[NN * FD];    // X@W buffer (reused across layers)
__device__ float g_h1[NN * FD];    // layer-1 output
__device__ float g_h2[NN * FD];    // layer-2 normalized embedding
__device__ float g_dinva[NN];      // adjacency dinv (GCN symmetric norm)
__device__ int   g_cnt[NN];        // adjacency in-degree counts
__device__ int   g_off[NN + 1];    // CSR offsets (by dst col)
__device__ int   g_cur[NN];        // scatter cursors
__device__ int   g_src[EE];        // CSR payload: source row of each in-edge
__device__ float g_deg[NN];        // learner-graph degree
__device__ float g_dinv[NN];       // learner-graph dinv
__device__ float g_s[EE];          // per-edge blended score s_val
__device__ float g_vs[EE];         // scratch mirror of out[2E..3E)
__device__ float g_v2[EE];         // scratch mirror of out[3E..4E)

// ---------------- kernels -------------------------------------------------

__global__ void k_init() {
    int n = blockIdx.x * blockDim.x + threadIdx.x;
    if (n < NN) { g_cnt[n] = 0; g_deg[n] = 0.0f; }
}

__global__ void k_count(const int* __restrict__ col) {
    int e = blockIdx.x * blockDim.x + threadIdx.x;
    if (e < EE) atomicAdd(&g_cnt[col[e]], 1);
}

// Single-block exclusive scan of g_cnt -> g_off/g_cur; also computes dinva.
__global__ void k_scan() {
    __shared__ int wsum[32];
    int t = threadIdx.x;
    int lane = t & 31, w = t >> 5;
    int carry = 0;
    for (int base = 0; base < NN; base += 1024) {
        int i = base + t;
        int v = (i < NN) ? g_cnt[i] : 0;
        int x = v;
#pragma unroll
        for (int d = 1; d < 32; d <<= 1) {
            int y = __shfl_up_sync(0xffffffffu, x, d);
            if (lane >= d) x += y;
        }
        if (lane == 31) wsum[w] = x;
        __syncthreads();
        if (w == 0) {
            int s = wsum[lane];
#pragma unroll
            for (int d = 1; d < 32; d <<= 1) {
                int y = __shfl_up_sync(0xffffffffu, s, d);
                if (lane >= d) s += y;
            }
            wsum[lane] = s;
        }
        __syncthreads();
        int incl = x + (w > 0 ? wsum[w - 1] : 0);
        int excl = carry + incl - v;
        if (i < NN) {
            g_off[i] = excl;
            g_cur[i] = excl;
            g_dinva[i] = rsqrtf(1.0f + (float)v);
        }
        carry += wsum[31];
        __syncthreads();
    }
    if (t == 0) g_off[NN] = carry;
}

__global__ void k_scatter(const int* __restrict__ row, const int* __restrict__ col) {
    int e = blockIdx.x * blockDim.x + threadIdx.x;
    if (e >= EE) return;
    int c = col[e];
    int pos = atomicAdd(&g_cur[c], 1);
    g_src[pos] = row[e];
}

// xw[r][c] = X[r][:] @ W[:][c]  (64x64 tile / block; float4 global loads)
__global__ void k_gemm(const float* __restrict__ X, const float* __restrict__ W,
                       float* __restrict__ xw, int relu_in) {
    __shared__ float sW[FD * FD];        // [k][c]
    __shared__ float sX[FD * 68];        // padded stride
    int t = threadIdx.x;
    int rowBase = blockIdx.x * FD;
    const float4* W4 = (const float4*)W;
    const float4* X4 = (const float4*)(X + rowBase * FD);
#pragma unroll
    for (int i = 0; i < 4; i++) {
        int idx = t + i * 256;           // 0..1023 float4 index
        float4 w = W4[idx];
        ((float4*)sW)[idx] = w;
        float4 x = X4[idx];
        if (relu_in) {
            x.x = fmaxf(x.x, 0.0f); x.y = fmaxf(x.y, 0.0f);
            x.z = fmaxf(x.z, 0.0f); x.w = fmaxf(x.w, 0.0f);
        }
        int r = idx >> 4, c4 = idx & 15;
        *(float4*)&sX[r * 68 + c4 * 4] = x;
    }
    __syncthreads();

    int tx = t & 15, ty = t >> 4;
    int c0 = tx * 4, r0 = ty * 4;
    float acc[4][4];
#pragma unroll
    for (int r = 0; r < 4; r++)
#pragma unroll
        for (int c = 0; c < 4; c++) acc[r][c] = 0.0f;

#pragma unroll
    for (int k = 0; k < FD; k++) {
        float4 bw = *(const float4*)&sW[k * FD + c0];
        float a0 = sX[(r0 + 0) * 68 + k];
        float a1 = sX[(r0 + 1) * 68 + k];
        float a2 = sX[(r0 + 2) * 68 + k];
        float a3 = sX[(r0 + 3) * 68 + k];
        acc[0][0] += a0 * bw.x; acc[0][1] += a0 * bw.y; acc[0][2] += a0 * bw.z; acc[0][3] += a0 * bw.w;
        acc[1][0] += a1 * bw.x; acc[1][1] += a1 * bw.y; acc[1][2] += a1 * bw.z; acc[1][3] += a1 * bw.w;
        acc[2][0] += a2 * bw.x; acc[2][1] += a2 * bw.y; acc[2][2] += a2 * bw.z; acc[2][3] += a2 * bw.w;
        acc[3][0] += a3 * bw.x; acc[3][1] += a3 * bw.y; acc[3][2] += a3 * bw.z; acc[3][3] += a3 * bw.w;
    }

#pragma unroll
    for (int rr = 0; rr < 4; rr++) {
        int r = rowBase + r0 + rr;
        *(float4*)&xw[r * FD + c0] = make_float4(acc[rr][0], acc[rr][1],
                                                 acc[rr][2], acc[rr][3]);
    }
}

// Warp per dst node: out[c] = b + dinva[c]^2*xw[c] + sum_in coef*xw[r]
// Source indices + dinva pre-loaded coalesced in chunks of 32, then
// shfl-broadcast -> independent back-to-back row loads (r11 exact form).
// mode 2: additionally L2-normalize the row (layer-2 epilogue fused).
__global__ void k_gather(const float* __restrict__ xw, float* __restrict__ out,
                         const float* __restrict__ b, int mode) {
    int tid = blockIdx.x * blockDim.x + threadIdx.x;
    int n = tid >> 5;
    if (n >= NN) return;
    int lane = tid & 31;
    float dc = g_dinva[n];
    float d2 = dc * dc;
    float2 a = ((const float2*)(xw + n * FD))[lane];
    float2 bb = ((const float2*)b)[lane];
    float2 acc = make_float2(bb.x + d2 * a.x, bb.y + d2 * a.y);
    int p0 = g_off[n], p1 = g_off[n + 1];
    for (int base = p0; base < p1; base += 32) {
        int cnt = min(32, p1 - base);
        int rsrc = 0;
        float din = 0.0f;
        if (base + lane < p1) {
            rsrc = __ldg(&g_src[base + lane]);
            din  = __ldg(&g_dinva[rsrc]);
        }
#pragma unroll 4
        for (int t = 0; t < cnt; t++) {
            int r = __shfl_sync(0xffffffffu, rsrc, t);
            float coef = dc * __shfl_sync(0xffffffffu, din, t);
            float2 v = ((const float2*)(xw + r * FD))[lane];
            acc.x += coef * v.x;
            acc.y += coef * v.y;
        }
    }
    if (mode == 2) {
        float s = acc.x * acc.x + acc.y * acc.y;
#pragma unroll
        for (int m = 16; m; m >>= 1) s += __shfl_xor_sync(0xffffffffu, s, m);
        float inv = 1.0f / fmaxf(sqrtf(s), 1e-12f);
        acc.x *= inv; acc.y *= inv;
    }
    ((float2*)(out + n * FD))[lane] = acc;
}

// Warp per node i: h[i] loaded once; 24 neighbor rows loaded coalesced.
__global__ void k_score(const float* __restrict__ h, const float* __restrict__ sd,
                        const int* __restrict__ jj) {
    int tid = blockIdx.x * blockDim.x + threadIdx.x;
    int n = tid >> 5;
    if (n >= NN) return;
    int lane = tid & 31;
    float2 hi = ((const float2*)(h + n * FD))[lane];
    int myj = 0; float mysd = 0.0f;
    if (lane < KNB) {
        myj  = __ldg(&jj[n * KNB + lane]);
        mysd = __ldg(&sd[n * KNB + lane]);
    }
    float mys = 0.0f;
#pragma unroll 4
    for (int t = 0; t < KNB; t++) {
        int j = __shfl_sync(0xffffffffu, myj, t);
        float2 hj = ((const float2*)(h + j * FD))[lane];
        float s = hi.x * hj.x + hi.y * hj.y;
#pragma unroll
        for (int m = 16; m; m >>= 1) s += __shfl_xor_sync(0xffffffffu, s, m);
        if (lane == t) mys = s;
    }
    if (lane < KNB)
        g_s[n * KNB + lane] = OMEGA_C * fmaxf(mys, 0.0f) + (1.0f - OMEGA_C) * mysd;
}

// Warp per node n. For each of its 24 edges (n, j_t): scan node j_t's
// candidate block COALESCED (lanes 0..23), ballot-match i==n, first set bit
// == reference's stable-argsort/searchsorted-left semantics. Writes vals_s
// halves into out[2E..4E) (unchanged) AND mirrors them into g_vs/g_v2 so
// k_fin never reads d_out back (the single change vs round-11).
__global__ void k_sym(const int* __restrict__ jj, float* __restrict__ out) {
    int tid = blockIdx.x * blockDim.x + threadIdx.x;
    int n = tid >> 5;
    if (n >= NN) return;
    int lane = tid & 31;
    int myj = 0; float mys = 0.0f;
    if (lane < KNB) {
        myj = __ldg(&jj[n * KNB + lane]);
        mys = g_s[n * KNB + lane];
    }
    float myvs = 0.0f, myv2 = 0.0f, degn = 0.0f;
    for (int t = 0; t < KNB; t++) {
        int j = __shfl_sync(0xffffffffu, myj, t);
        float sv = __shfl_sync(0xffffffffu, mys, t);
        int cand = (lane < KNB) ? __ldg(&jj[j * KNB + lane]) : -1;
        unsigned m = __ballot_sync(0xffffffffu, cand == n);
        float vsym, v2;
        if (m) {                                   // uniform branch
            int idx = __ffs(m) - 1;
            float srev = g_s[j * KNB + idx];       // uniform broadcast load
            vsym = 0.5f * (sv + srev); v2 = 0.0f;
        } else {
            vsym = sv; v2 = sv;
            if (lane == 0) atomicAdd(&g_deg[j], vsym);
        }
        degn += vsym;
        if (lane == t) { myvs = vsym; myv2 = v2; }
    }
    if (lane == 0) atomicAdd(&g_deg[n], degn);
    if (lane < KNB) {
        out[2 * EE + n * KNB + lane] = myvs;
        out[3 * EE + n * KNB + lane] = myv2;
        g_vs[n * KNB + lane] = myvs;   // scratch mirror (device-resident)
        g_v2[n * KNB + lane] = myv2;
    }
}

__global__ void k_dinv() {
    int n = blockIdx.x * blockDim.x + threadIdx.x;
    if (n < NN) {
        float d = g_deg[n];
        g_dinv[n] = (d > 0.0f) ? rsqrtf(fmaxf(d, 1e-12f)) : 0.0f;
    }
}

// vals_norm = dinv[i]*vals_s*dinv[j]; i = e/24 (i_idx structure), coalesced.
// Reads the device scratch mirrors (g_vs/g_v2) — never reads d_out back.
__global__ void k_fin(const int* __restrict__ jj, float* __restrict__ out) {
    int e = blockIdx.x * blockDim.x + threadIdx.x;
    if (e >= EE) return;
    int i = e / KNB;
    float c = g_dinv[i] * __ldg(&g_dinv[jj[e]]);
    out[e]      = c * g_vs[e];
    out[EE + e] = c * g_v2[e];
}

// ---------------- launcher ------------------------------------------------

extern "C" void kernel_launch(void* const* d_in, const int* in_sizes, int n_in,
                              void* d_out, int out_size) {
    const float* features = (const float*)d_in[0];
    const float* W1       = (const float*)d_in[1];
    const float* b1       = (const float*)d_in[2];
    const float* W2       = (const float*)d_in[3];
    const float* b2       = (const float*)d_in[4];
    const float* s_d      = (const float*)d_in[5];
    const int*   adj_row  = (const int*)d_in[6];
    const int*   adj_col  = (const int*)d_in[7];
    const int*   j_idx    = (const int*)d_in[9];
    float* out = (float*)d_out;

    const int BN = (NN + 255) / 256;
    const int BE = (EE + 255) / 256;
    const int BW = (32 * NN + 255) / 256;     // warp per node
    const int BG = NN / FD;                   // 625 gemm tiles

    // CSR build (fixed adjacency; once per launch) — proven 12-launch skeleton
    k_init<<<BN, 256>>>();
    k_count<<<BE, 256>>>(adj_col);
    k_scan<<<1, 1024>>>();
    k_scatter<<<BE, 256>>>(adj_row, adj_col);

    // GCN layer 1 (relu fused into next gemm's load)
    k_gemm<<<BG, 256>>>(features, W1, g_xw, 0);
    k_gather<<<BW, 256>>>(g_xw, g_h1, b1, 1);

    // GCN layer 2 + fused row L2-normalize
    k_gemm<<<BG, 256>>>(g_h1, W2, g_xw, 1);
    k_gather<<<BW, 256>>>(g_xw, g_h2, b2, 2);

    // edge scores (warp per node)
    k_score<<<BW, 256>>>(g_h2, s_d, j_idx);

    // symmetrize + degree + final normalization (fin reads scratch, not out)
    k_sym<<<BW, 256>>>(j_idx, out);
    k_dinv<<<BN, 256>>>();
    k_fin<<<BE, 256>>>(j_idx, out);

    (void)in_sizes; (void)n_in; (void)out_size;
}

// round 17
// speedup vs baseline: 1.0136x; 1.0136x over previous
#include <cuda_runtime.h>
#include <cuda_bf16.h>

// Problem constants (fixed shapes from reference setup_inputs)
#define NN 40000
#define FD 64
#define KNB 24
#define EE (NN * KNB)        // 960000 candidate edges (= E_ADJ too)
#define OMEGA_C 0.9f

// ---------------- scratch (device globals; no allocation allowed) ----------
__device__ float g_xw[NN * FD];    // X@W buffer (reused across layers)
__device__ float g_h1[NN * FD];    // layer-1 output
__device__ float g_h2[NN * FD];    // layer-2 normalized embedding
__device__ float g_dinva[NN];      // adjacency dinv (GCN symmetric norm)
__device__ int   g_cnt[NN];        // adjacency in-degree counts
__device__ int   g_off[NN + 1];    // CSR offsets (by dst col)
__device__ int   g_cur[NN];        // scatter cursors
__device__ int   g_src[EE];        // CSR payload: source row of each in-edge
__device__ float g_deg[NN];        // learner-graph degree
__device__ float g_dinv[NN];       // learner-graph dinv
__device__ float g_s[EE];          // per-edge blended score s_val

// ---------------- kernels -------------------------------------------------

__global__ void k_init() {
    int n = blockIdx.x * blockDim.x + threadIdx.x;
    if (n < NN) { g_cnt[n] = 0; g_deg[n] = 0.0f; }
}

__global__ void k_count(const int* __restrict__ col) {
    int e = blockIdx.x * blockDim.x + threadIdx.x;
    if (e < EE) atomicAdd(&g_cnt[col[e]], 1);
}

// Single-block exclusive scan of g_cnt -> g_off/g_cur; also computes dinva.
__global__ void k_scan() {
    __shared__ int wsum[32];
    int t = threadIdx.x;
    int lane = t & 31, w = t >> 5;
    int carry = 0;
    for (int base = 0; base < NN; base += 1024) {
        int i = base + t;
        int v = (i < NN) ? g_cnt[i] : 0;
        int x = v;
#pragma unroll
        for (int d = 1; d < 32; d <<= 1) {
            int y = __shfl_up_sync(0xffffffffu, x, d);
            if (lane >= d) x += y;
        }
        if (lane == 31) wsum[w] = x;
        __syncthreads();
        if (w == 0) {
            int s = wsum[lane];
#pragma unroll
            for (int d = 1; d < 32; d <<= 1) {
                int y = __shfl_up_sync(0xffffffffu, s, d);
                if (lane >= d) s += y;
            }
            wsum[lane] = s;
        }
        __syncthreads();
        int incl = x + (w > 0 ? wsum[w - 1] : 0);
        int excl = carry + incl - v;
        if (i < NN) {
            g_off[i] = excl;
            g_cur[i] = excl;
            g_dinva[i] = rsqrtf(1.0f + (float)v);
        }
        carry += wsum[31];
        __syncthreads();
    }
    if (t == 0) g_off[NN] = carry;
}

__global__ void k_scatter(const int* __restrict__ row, const int* __restrict__ col) {
    int e = blockIdx.x * blockDim.x + threadIdx.x;
    if (e >= EE) return;
    int c = col[e];
    int pos = atomicAdd(&g_cur[c], 1);
    g_src[pos] = row[e];
}

// xw[r][c] = X[r][:] @ W[:][c]  (64x64 tile / block; float4 global loads)
__global__ void k_gemm(const float* __restrict__ X, const float* __restrict__ W,
                       float* __restrict__ xw, int relu_in) {
    __shared__ float sW[FD * FD];        // [k][c]
    __shared__ float sX[FD * 68];        // padded stride
    int t = threadIdx.x;
    int rowBase = blockIdx.x * FD;
    const float4* W4 = (const float4*)W;
    const float4* X4 = (const float4*)(X + rowBase * FD);
#pragma unroll
    for (int i = 0; i < 4; i++) {
        int idx = t + i * 256;           // 0..1023 float4 index
        float4 w = W4[idx];
        ((float4*)sW)[idx] = w;
        float4 x = X4[idx];
        if (relu_in) {
            x.x = fmaxf(x.x, 0.0f); x.y = fmaxf(x.y, 0.0f);
            x.z = fmaxf(x.z, 0.0f); x.w = fmaxf(x.w, 0.0f);
        }
        int r = idx >> 4, c4 = idx & 15;
        *(float4*)&sX[r * 68 + c4 * 4] = x;
    }
    __syncthreads();

    int tx = t & 15, ty = t >> 4;
    int c0 = tx * 4, r0 = ty * 4;
    float acc[4][4];
#pragma unroll
    for (int r = 0; r < 4; r++)
#pragma unroll
        for (int c = 0; c < 4; c++) acc[r][c] = 0.0f;

#pragma unroll
    for (int k = 0; k < FD; k++) {
        float4 bw = *(const float4*)&sW[k * FD + c0];
        float a0 = sX[(r0 + 0) * 68 + k];
        float a1 = sX[(r0 + 1) * 68 + k];
        float a2 = sX[(r0 + 2) * 68 + k];
        float a3 = sX[(r0 + 3) * 68 + k];
        acc[0][0] += a0 * bw.x; acc[0][1] += a0 * bw.y; acc[0][2] += a0 * bw.z; acc[0][3] += a0 * bw.w;
        acc[1][0] += a1 * bw.x; acc[1][1] += a1 * bw.y; acc[1][2] += a1 * bw.z; acc[1][3] += a1 * bw.w;
        acc[2][0] += a2 * bw.x; acc[2][1] += a2 * bw.y; acc[2][2] += a2 * bw.z; acc[2][3] += a2 * bw.w;
        acc[3][0] += a3 * bw.x; acc[3][1] += a3 * bw.y; acc[3][2] += a3 * bw.z; acc[3][3] += a3 * bw.w;
    }

#pragma unroll
    for (int rr = 0; rr < 4; rr++) {
        int r = rowBase + r0 + rr;
        *(float4*)&xw[r * FD + c0] = make_float4(acc[rr][0], acc[rr][1],
                                                 acc[rr][2], acc[rr][3]);
    }
}

// Warp per dst node: out[c] = b + dinva[c]^2*xw[c] + sum_in coef*xw[r]
// Source indices + dinva pre-loaded coalesced in chunks of 32, then
// shfl-broadcast -> independent back-to-back row loads.
// mode 2: additionally L2-normalize the row (layer-2 epilogue fused).
__global__ void k_gather(const float* __restrict__ xw, float* __restrict__ out,
                         const float* __restrict__ b, int mode) {
    int tid = blockIdx.x * blockDim.x + threadIdx.x;
    int n = tid >> 5;
    if (n >= NN) return;
    int lane = tid & 31;
    float dc = g_dinva[n];
    float d2 = dc * dc;
    float2 a = ((const float2*)(xw + n * FD))[lane];
    float2 bb = ((const float2*)b)[lane];
    float2 acc = make_float2(bb.x + d2 * a.x, bb.y + d2 * a.y);
    int p0 = g_off[n], p1 = g_off[n + 1];
    for (int base = p0; base < p1; base += 32) {
        int cnt = min(32, p1 - base);
        int rsrc = 0;
        float din = 0.0f;
        if (base + lane < p1) {
            rsrc = __ldg(&g_src[base + lane]);
            din  = __ldg(&g_dinva[rsrc]);
        }
#pragma unroll 4
        for (int t = 0; t < cnt; t++) {
            int r = __shfl_sync(0xffffffffu, rsrc, t);
            float coef = dc * __shfl_sync(0xffffffffu, din, t);
            float2 v = ((const float2*)(xw + r * FD))[lane];
            acc.x += coef * v.x;
            acc.y += coef * v.y;
        }
    }
    if (mode == 2) {
        float s = acc.x * acc.x + acc.y * acc.y;
#pragma unroll
        for (int m = 16; m; m >>= 1) s += __shfl_xor_sync(0xffffffffu, s, m);
        float inv = 1.0f / fmaxf(sqrtf(s), 1e-12f);
        acc.x *= inv; acc.y *= inv;
    }
    ((float2*)(out + n * FD))[lane] = acc;
}

// Warp per node i: h[i] loaded once; 24 neighbor rows loaded coalesced.
__global__ void k_score(const float* __restrict__ h, const float* __restrict__ sd,
                        const int* __restrict__ jj) {
    int tid = blockIdx.x * blockDim.x + threadIdx.x;
    int n = tid >> 5;
    if (n >= NN) return;
    int lane = tid & 31;
    float2 hi = ((const float2*)(h + n * FD))[lane];
    int myj = 0; float mysd = 0.0f;
    if (lane < KNB) {
        myj  = __ldg(&jj[n * KNB + lane]);
        mysd = __ldg(&sd[n * KNB + lane]);
    }
    float mys = 0.0f;
#pragma unroll 4
    for (int t = 0; t < KNB; t++) {
        int j = __shfl_sync(0xffffffffu, myj, t);
        float2 hj = ((const float2*)(h + j * FD))[lane];
        float s = hi.x * hj.x + hi.y * hj.y;
#pragma unroll
        for (int m = 16; m; m >>= 1) s += __shfl_xor_sync(0xffffffffu, s, m);
        if (lane == t) mys = s;
    }
    if (lane < KNB)
        g_s[n * KNB + lane] = OMEGA_C * fmaxf(mys, 0.0f) + (1.0f - OMEGA_C) * mysd;
}

// Warp per node n. For each of its 24 edges (n, j_t): scan node j_t's
// candidate block COALESCED (lanes 0..23), ballot-match i==n, first set bit
// == reference's stable-argsort/searchsorted-left semantics. Writes vals_s
// halves into out[2E..4E); accumulates learner degrees (batched for n).
__global__ void k_sym(const int* __restrict__ jj, float* __restrict__ out) {
    int tid = blockIdx.x * blockDim.x + threadIdx.x;
    int n = tid >> 5;
    if (n >= NN) return;
    int lane = tid & 31;
    int myj = 0; float mys = 0.0f;
    if (lane < KNB) {
        myj = __ldg(&jj[n * KNB + lane]);
        mys = g_s[n * KNB + lane];
    }
    float myvs = 0.0f, myv2 = 0.0f, degn = 0.0f;
    for (int t = 0; t < KNB; t++) {
        int j = __shfl_sync(0xffffffffu, myj, t);
        float sv = __shfl_sync(0xffffffffu, mys, t);
        int cand = (lane < KNB) ? __ldg(&jj[j * KNB + lane]) : -1;
        unsigned m = __ballot_sync(0xffffffffu, cand == n);
        float vsym, v2;
        if (m) {                                   // uniform branch
            int idx = __ffs(m) - 1;
            float srev = g_s[j * KNB + idx];       // uniform broadcast load
            vsym = 0.5f * (sv + srev); v2 = 0.0f;
        } else {
            vsym = sv; v2 = sv;
            if (lane == 0) atomicAdd(&g_deg[j], vsym);
        }
        degn += vsym;
        if (lane == t) { myvs = vsym; myv2 = v2; }
    }
    if (lane == 0) atomicAdd(&g_deg[n], degn);
    if (lane < KNB) {
        out[2 * EE + n * KNB + lane] = myvs;
        out[3 * EE + n * KNB + lane] = myv2;
    }
}

__global__ void k_dinv() {
    int n = blockIdx.x * blockDim.x + threadIdx.x;
    if (n < NN) {
        float d = g_deg[n];
        g_dinv[n] = (d > 0.0f) ? rsqrtf(fmaxf(d, 1e-12f)) : 0.0f;
    }
}

// vals_norm = dinv[i]*vals_s*dinv[j]; i = e/24 (i_idx structure), coalesced.
__global__ void k_fin(const int* __restrict__ jj, float* __restrict__ out) {
    int e = blockIdx.x * blockDim.x + threadIdx.x;
    if (e >= EE) return;
    int i = e / KNB;
    float c = g_dinv[i] * __ldg(&g_dinv[jj[e]]);
    out[e]      = c * out[2 * EE + e];
    out[EE + e] = c * out[3 * EE + e];
}

// ---------------- launcher ------------------------------------------------

extern "C" void kernel_launch(void* const* d_in, const int* in_sizes, int n_in,
                              void* d_out, int out_size) {
    const float* features = (const float*)d_in[0];
    const float* W1       = (const float*)d_in[1];
    const float* b1       = (const float*)d_in[2];
    const float* W2       = (const float*)d_in[3];
    const float* b2       = (const float*)d_in[4];
    const float* s_d      = (const float*)d_in[5];
    const int*   adj_row  = (const int*)d_in[6];
    const int*   adj_col  = (const int*)d_in[7];
    const int*   j_idx    = (const int*)d_in[9];
    float* out = (float*)d_out;

    const int BN = (NN + 255) / 256;
    const int BE = (EE + 255) / 256;
    const int BW = (32 * NN + 255) / 256;     // warp per node
    const int BG = NN / FD;                   // 625 gemm tiles

    // CSR build (fixed adjacency; once per launch) — proven 12-launch skeleton
    k_init<<<BN, 256>>>();
    k_count<<<BE, 256>>>(adj_col);
    k_scan<<<1, 1024>>>();
    k_scatter<<<BE, 256>>>(adj_row, adj_col);

    // GCN layer 1 (relu fused into next gemm's load)
    k_gemm<<<BG, 256>>>(features, W1, g_xw, 0);
    k_gather<<<BW, 256>>>(g_xw, g_h1, b1, 1);

    // GCN layer 2 + fused row L2-normalize
    k_gemm<<<BG, 256>>>(g_h1, W2, g_xw, 1);
    k_gather<<<BW, 256>>>(g_xw, g_h2, b2, 2);

    // edge scores (warp per node)
    k_score<<<BW, 256>>>(g_h2, s_d, j_idx);

    // symmetrize + degree + final normalization
    k_sym<<<BW, 256>>>(j_idx, out);
    k_dinv<<<BN, 256>>>();
    k_fin<<<BE, 256>>>(j_idx, out);

    (void)in_sizes; (void)n_in; (void)out_size;
}